// round 2
// baseline (speedup 1.0000x reference)
#include <cuda_runtime.h>
#include <cstdint>

// ---------------------------------------------------------------------------
// Kagome 3x3 conv: pad 16x16 -> 18x18 (stride 20 in smem), 37 boundary
// copies, VALID 3x3 conv, +bias, *mask.  B=2048, Cin=Cout=128, fp32.
//
// CTA: one image x 64 output channels. 256 threads; each thread: 8 px x 8 co
// accumulated as f32x2 pairs (fma.rn.f32x2 = 2x FFMA throughput).
// R2 changes vs R1 (l1tex was 94% -> LDS-bound):
//   - x smem row stride 20 -> float4/float2 vector loads (9 LDS/ci vs 30)
//   - W loaded as ulonglong2 (pre-paired f32x2, no repacking movs)
//   - x splats hoisted per row, reused across the 3 kc taps
// ---------------------------------------------------------------------------

#define CK 8
#define XSTR 20

__constant__ int FDR[37] = {1,1,2,3,4,4,6,7,8,10,11,12,14,14,15,16,17,17,16,15,14,14,12,10,8,6,4,4,3,2,5,9,13,15,17,15,13};
__constant__ int FDC[37] = {3,5,7,9,10,11,13,13,14,15,15,16,15,16,15,14,13,11,9,7,6,5,3,2,1,0,0,1,1,2,0,2,4,8,12,14,16};
__constant__ int FSR[37] = {13,13,14,15,16,16,6,7,8,10,11,12,2,2,3,4,5,5,4,3,2,2,12,10,8,6,16,16,15,14,5,9,1,3,5,3,1};
__constant__ int FSC[37] = {15,5,7,9,10,11,1,1,2,3,3,4,3,4,3,2,1,11,9,7,6,5,15,14,13,12,12,13,13,14,12,14,4,8,12,2,4};

__constant__ unsigned MASKROW[16] = {
    0x0008u, 0x003Cu, 0x00FEu, 0x01FEu,
    0x0FFFu, 0x0FFFu, 0x0FFFu, 0x1FFEu,
    0x3FFCu, 0x3FFCu, 0x3FFCu, 0x7FF8u,
    0x7FF0u, 0x3FC0u, 0x1F00u, 0x1E00u
};

__device__ __forceinline__ unsigned long long pack2(float a, float b) {
    unsigned long long r;
    asm("mov.b64 %0, {%1, %2};" : "=l"(r) : "f"(a), "f"(b));
    return r;
}
__device__ __forceinline__ void unpack2(unsigned long long v, float& a, float& b) {
    asm("mov.b64 {%0, %1}, %2;" : "=f"(a), "=f"(b) : "l"(v));
}
__device__ __forceinline__ unsigned long long fma2(unsigned long long a,
                                                   unsigned long long b,
                                                   unsigned long long c) {
    unsigned long long d;
    asm("fma.rn.f32x2 %0, %1, %2, %3;" : "=l"(d) : "l"(a), "l"(b), "l"(c));
    return d;
}

__global__ void __launch_bounds__(256)
kagome_conv_kernel(const float* __restrict__ x,
                   const float* __restrict__ W,
                   const float* __restrict__ b,
                   float* __restrict__ out) {
    __shared__ __align__(16) float xs[CK][18 * XSTR];   // padded tile, stride 20
    __shared__ __align__(16) float ws[CK][9][64];       // W[ci][k][co]

    const int n      = blockIdx.y;
    const int coBase = blockIdx.x * 64;
    const int tid    = threadIdx.x;
    const int coT    = tid & 7;
    const int pxT    = tid >> 3;
    const int r      = pxT >> 1;
    const int c0     = (pxT & 1) * 8;

    // zero whole padded tile once; non-fixup border cells stay 0 forever
    for (int i = tid; i < CK * 18 * XSTR; i += 256) (&xs[0][0])[i] = 0.f;

    unsigned long long acc[8][4];
    #pragma unroll
    for (int p = 0; p < 8; p++)
        #pragma unroll
        for (int q = 0; q < 4; q++) acc[p][q] = 0ull;

    const float* xg = x + (size_t)n * 128 * 256;
    const float* Wg = W + (size_t)coBase * 128 * 9;

    for (int cb = 0; cb < 128; cb += CK) {
        __syncthreads();

        // interior fill (coalesced)
        #pragma unroll
        for (int i = 0; i < CK; i++) {
            int idx = tid + i * 256;
            int ci = idx >> 8, px = idx & 255;
            xs[ci][(px >> 4) * XSTR + (px & 15) + XSTR + 1] = xg[(cb + ci) * 256 + px];
        }
        __syncthreads();   // interior visible before fixups overwrite

        // 37 boundary fixups per channel (sources read from original gmem x)
        for (int j = tid; j < CK * 37; j += 256) {
            int ci = j / 37, f = j - ci * 37;
            xs[ci][FDR[f] * XSTR + FDC[f]] =
                xg[(cb + ci) * 256 + (FSR[f] - 1) * 16 + (FSC[f] - 1)];
        }
        // stage W chunk as [ci][k][co]
        #pragma unroll
        for (int i = 0; i < CK * 9 * 64 / 256; i++) {
            int idx = tid + i * 256;
            int ci = idx / 576, rem = idx - ci * 576;
            int k = rem >> 6, co = rem & 63;
            ws[ci][k][co] = Wg[co * 1152 + (cb + ci) * 9 + k];
        }
        __syncthreads();

        #pragma unroll 1
        for (int ci = 0; ci < CK; ci++) {
            const float* xb = &xs[ci][r * XSTR + c0];
            #pragma unroll
            for (int kr = 0; kr < 3; kr++) {
                float4 va = *reinterpret_cast<const float4*>(xb + kr * XSTR);
                float4 vb = *reinterpret_cast<const float4*>(xb + kr * XSTR + 4);
                float2 vc = *reinterpret_cast<const float2*>(xb + kr * XSTR + 8);
                float xr[10] = {va.x, va.y, va.z, va.w,
                                vb.x, vb.y, vb.z, vb.w, vc.x, vc.y};
                unsigned long long xd[10];
                #pragma unroll
                for (int j = 0; j < 10; j++) xd[j] = pack2(xr[j], xr[j]);
                #pragma unroll
                for (int kc = 0; kc < 3; kc++) {
                    const ulonglong2* wp = reinterpret_cast<const ulonglong2*>(
                        &ws[ci][kr * 3 + kc][coT * 8]);
                    ulonglong2 wA = wp[0];
                    ulonglong2 wB = wp[1];
                    #pragma unroll
                    for (int p = 0; p < 8; p++) {
                        unsigned long long xv = xd[p + kc];
                        acc[p][0] = fma2(xv, wA.x, acc[p][0]);
                        acc[p][1] = fma2(xv, wA.y, acc[p][1]);
                        acc[p][2] = fma2(xv, wB.x, acc[p][2]);
                        acc[p][3] = fma2(xv, wB.y, acc[p][3]);
                    }
                }
            }
        }
    }

    // epilogue: +bias, *mask, store
    const unsigned mrow = MASKROW[r];
    const int coLoc = coBase + coT * 8;
    float bias[8];
    #pragma unroll
    for (int j = 0; j < 8; j++) bias[j] = b[coLoc + j];

    const size_t outBase = ((size_t)n * 128 + coLoc) * 256 + r * 16 + c0;
    #pragma unroll
    for (int q = 0; q < 4; q++) {
        float o0[8], o1[8];
        #pragma unroll
        for (int p = 0; p < 8; p++) {
            float v0, v1;
            unpack2(acc[p][q], v0, v1);
            float m = ((mrow >> (c0 + p)) & 1u) ? 1.f : 0.f;
            o0[p] = (v0 + bias[2 * q]) * m;
            o1[p] = (v1 + bias[2 * q + 1]) * m;
        }
        float4* d0 = reinterpret_cast<float4*>(out + outBase + (size_t)(2 * q) * 256);
        float4* d1 = reinterpret_cast<float4*>(out + outBase + (size_t)(2 * q + 1) * 256);
        d0[0] = make_float4(o0[0], o0[1], o0[2], o0[3]);
        d0[1] = make_float4(o0[4], o0[5], o0[6], o0[7]);
        d1[0] = make_float4(o1[0], o1[1], o1[2], o1[3]);
        d1[1] = make_float4(o1[4], o1[5], o1[6], o1[7]);
    }
}

extern "C" void kernel_launch(void* const* d_in, const int* in_sizes, int n_in,
                              void* d_out, int out_size) {
    (void)in_sizes; (void)n_in; (void)out_size;
    const float* x = (const float*)d_in[0];
    const float* W = (const float*)d_in[1];
    const float* b = (const float*)d_in[2];
    float* out = (float*)d_out;

    dim3 grid(2, 2048);
    kagome_conv_kernel<<<grid, 256>>>(x, W, b, out);
}

// round 4
// speedup vs baseline: 2.6424x; 2.6424x over previous
#include <cuda_runtime.h>
#include <cuda_bf16.h>
#include <cstdint>

// ===========================================================================
// Kagome conv as implicit GEMM on mma.sync (bf16 hi/lo 3-pass, fp32 accum).
// tcgen05 is unavailable (harness PTX target is compute_103, ptxas rejects
// the 'a'-only features), so we use sm_80-class mma.sync.m16n8k16.bf16 which
// runs on the tensor pipe and compiles for plain sm_103.
//
// Per CTA = one image. D[256 px, 128 co], K = 9 taps x 128 ci x 3 splits.
// 512 threads = 16 warps = 4 (px) x 4 (co) warp tiles of 64px x 32co.
// Padded image in smem as xp2[18*18 pos][128 ci] u32 = bf16hi | bf16lo<<16,
// ci permuted within 16-groups so an A fragment quad is one LDS.128.
// W pre-split/permuted once into a __device__ global; B frags via LDG.128.
// ===========================================================================

__constant__ int FDR[37] = {1,1,2,3,4,4,6,7,8,10,11,12,14,14,15,16,17,17,16,15,14,14,12,10,8,6,4,4,3,2,5,9,13,15,17,15,13};
__constant__ int FDC[37] = {3,5,7,9,10,11,13,13,14,15,15,16,15,16,15,14,13,11,9,7,6,5,3,2,1,0,0,1,1,2,0,2,4,8,12,14,16};
__constant__ int FSR[37] = {13,13,14,15,16,16,6,7,8,10,11,12,2,2,3,4,5,5,4,3,2,2,12,10,8,6,16,16,15,14,5,9,1,3,5,3,1};
__constant__ int FSC[37] = {15,5,7,9,10,11,1,1,2,3,3,4,3,4,3,2,1,11,9,7,6,5,15,14,13,12,12,13,13,14,12,14,4,8,12,2,4};

__constant__ unsigned MASKROW[16] = {
    0x0008u, 0x003Cu, 0x00FEu, 0x01FEu,
    0x0FFFu, 0x0FFFu, 0x0FFFu, 0x1FFEu,
    0x3FFCu, 0x3FFCu, 0x3FFCu, 0x7FF8u,
    0x7FF0u, 0x3FC0u, 0x1F00u, 0x1E00u
};

// W split+permuted: [tap][co][ci_perm], u32 = bf16hi | bf16lo<<16
__device__ unsigned int Wt[9][128][128];

#define PAD 144                 // u32 per pos-row (18*8; conflict-free LDS.128)
#define SMEM_BYTES (324 * PAD * 4)   // 186,624 B

static __device__ __forceinline__ uint32_t pack_hl(float v) {
    __nv_bfloat16 h = __float2bfloat16(v);
    float hv = __bfloat162float(h);
    __nv_bfloat16 l = __float2bfloat16(v - hv);
    return (uint32_t)__bfloat16_as_ushort(h) |
           ((uint32_t)__bfloat16_as_ushort(l) << 16);
}

// slot within a 16-ci group so that quad q owns u32 slots 4q..4q+3 holding
// k = 2q, 2q+1, 2q+8, 2q+9
static __device__ __forceinline__ int slot16(int k) {
    return ((k & 7) >> 1) * 4 + (k & 1) + ((k >> 3) << 1);
}

static __device__ __forceinline__ void mma_bf16(float* c, const uint32_t* a,
                                                uint32_t b0, uint32_t b1) {
    asm volatile(
        "mma.sync.aligned.m16n8k16.row.col.f32.bf16.bf16.f32 "
        "{%0,%1,%2,%3}, {%4,%5,%6,%7}, {%8,%9}, {%0,%1,%2,%3};"
        : "+f"(c[0]), "+f"(c[1]), "+f"(c[2]), "+f"(c[3])
        : "r"(a[0]), "r"(a[1]), "r"(a[2]), "r"(a[3]), "r"(b0), "r"(b1));
}

// ---------------- prep: W -> Wt[tap][co][ci_perm] ----------------
__global__ void prep_w_kernel(const float* __restrict__ W) {
    int idx = blockIdx.x * 256 + threadIdx.x;
    if (idx >= 9 * 128 * 128) return;
    int tap = idx >> 14;
    int co  = (idx >> 7) & 127;
    int ci  = idx & 127;
    uint32_t p = pack_hl(W[co * 1152 + ci * 9 + tap]);
    Wt[tap][co][(ci >> 4) * 16 + slot16(ci & 15)] = p;
}

// ---------------- main ----------------
__global__ void __launch_bounds__(512, 1)
kagome_mma_kernel(const float* __restrict__ x,
                  const float* __restrict__ b,
                  float* __restrict__ out) {
    extern __shared__ uint32_t xp2[];   // [324 pos][PAD] ; data in first 128 u32

    const int tid   = threadIdx.x;
    const int wid   = tid >> 5;
    const int lane  = tid & 31;
    const int q     = lane & 3;     // k-quad
    const int lr    = lane >> 2;    // frag row / B col
    const int warpM = wid & 3;      // px-row group (4 image rows)
    const int warpN = wid >> 2;     // co group of 32
    const int img   = blockIdx.x;

    const float* xg = x + (size_t)img * 128 * 256;

    // ---- stage padded image ----
    {
        uint4* z = (uint4*)xp2;
        #pragma unroll
        for (int i = 0; i < 23; i++) {
            int j = tid + i * 512;
            if (j < 324 * PAD / 4) z[j] = make_uint4(0, 0, 0, 0);
        }
    }
    __syncthreads();
    #pragma unroll
    for (int i = 0; i < 64; i++) {
        int idx = tid + i * 512;             // = ci*256 + px
        int ci = idx >> 8, px = idx & 255;
        uint32_t p = pack_hl(xg[idx]);
        int pos = ((px >> 4) + 1) * 18 + (px & 15) + 1;
        xp2[pos * PAD + (ci >> 4) * 16 + slot16(ci & 15)] = p;
    }
    __syncthreads();   // interior visible before fixups overwrite
    for (int j = tid; j < 128 * 37; j += 512) {
        int ci = j / 37, f = j - ci * 37;
        uint32_t p = pack_hl(xg[ci * 256 + (FSR[f] - 1) * 16 + (FSC[f] - 1)]);
        int pos = FDR[f] * 18 + FDC[f];
        xp2[pos * PAD + (ci >> 4) * 16 + slot16(ci & 15)] = p;
    }
    __syncthreads();

    // ---- mainloop ----
    float C[4][4][4];
    #pragma unroll
    for (int s = 0; s < 4; s++)
        #pragma unroll
        for (int n = 0; n < 4; n++)
            #pragma unroll
            for (int e = 0; e < 4; e++) C[s][n][e] = 0.f;

    for (int tap = 0; tap < 9; tap++) {
        const int kr = tap / 3, kc = tap - kr * 3;
        #pragma unroll
        for (int g = 0; g < 8; g++) {
            // A fragments for 4 m-subtiles (image rows warpM*4+s)
            uint32_t ah[4][4], al[4][4];
            #pragma unroll
            for (int s = 0; s < 4; s++) {
                int R = warpM * 4 + s;
                int base = ((R + kr) * 18 + kc) * PAD + g * 16 + q * 4;
                uint4 v0 = *(const uint4*)(xp2 + base + lr * PAD);
                uint4 v1 = *(const uint4*)(xp2 + base + (lr + 8) * PAD);
                ah[s][0] = __byte_perm(v0.x, v0.y, 0x5410);
                ah[s][2] = __byte_perm(v0.z, v0.w, 0x5410);
                ah[s][1] = __byte_perm(v1.x, v1.y, 0x5410);
                ah[s][3] = __byte_perm(v1.z, v1.w, 0x5410);
                al[s][0] = __byte_perm(v0.x, v0.y, 0x7632);
                al[s][2] = __byte_perm(v0.z, v0.w, 0x7632);
                al[s][1] = __byte_perm(v1.x, v1.y, 0x7632);
                al[s][3] = __byte_perm(v1.z, v1.w, 0x7632);
            }
            #pragma unroll
            for (int ns = 0; ns < 4; ns++) {
                int co = warpN * 32 + ns * 8 + lr;
                uint4 w = __ldg((const uint4*)&Wt[tap][co][g * 16 + q * 4]);
                uint32_t bh0 = __byte_perm(w.x, w.y, 0x5410);
                uint32_t bh1 = __byte_perm(w.z, w.w, 0x5410);
                uint32_t bl0 = __byte_perm(w.x, w.y, 0x7632);
                uint32_t bl1 = __byte_perm(w.z, w.w, 0x7632);
                #pragma unroll
                for (int s = 0; s < 4; s++) mma_bf16(C[s][ns], ah[s], bh0, bh1);
                #pragma unroll
                for (int s = 0; s < 4; s++) mma_bf16(C[s][ns], al[s], bh0, bh1);
                #pragma unroll
                for (int s = 0; s < 4; s++) mma_bf16(C[s][ns], ah[s], bl0, bl1);
            }
        }
    }

    // ---- epilogue: +bias, *mask, store ----
    float* og = out + (size_t)img * 128 * 256;
    #pragma unroll
    for (int ns = 0; ns < 4; ns++) {
        int co0 = warpN * 32 + ns * 8 + 2 * q;
        float bv0 = __ldg(b + co0);
        float bv1 = __ldg(b + co0 + 1);
        #pragma unroll
        for (int s = 0; s < 4; s++) {
            int R = warpM * 4 + s;
            unsigned mrow = MASKROW[R];
            float k0 = ((mrow >> lr) & 1u) ? 1.f : 0.f;        // col lr
            float k1 = ((mrow >> (lr + 8)) & 1u) ? 1.f : 0.f;  // col lr+8
            int p0 = R * 16 + lr;
            int p1 = p0 + 8;
            og[co0 * 256 + p0]       = (C[s][ns][0] + bv0) * k0;
            og[(co0 + 1) * 256 + p0] = (C[s][ns][1] + bv1) * k0;
            og[co0 * 256 + p1]       = (C[s][ns][2] + bv0) * k1;
            og[(co0 + 1) * 256 + p1] = (C[s][ns][3] + bv1) * k1;
        }
    }
}

extern "C" void kernel_launch(void* const* d_in, const int* in_sizes, int n_in,
                              void* d_out, int out_size) {
    (void)in_sizes; (void)n_in; (void)out_size;
    const float* x = (const float*)d_in[0];
    const float* W = (const float*)d_in[1];
    const float* b = (const float*)d_in[2];
    float* out = (float*)d_out;

    cudaFuncSetAttribute(kagome_mma_kernel,
                         cudaFuncAttributeMaxDynamicSharedMemorySize, SMEM_BYTES);

    prep_w_kernel<<<(9 * 128 * 128 + 255) / 256, 256>>>(W);
    kagome_mma_kernel<<<2048, 512, SMEM_BYTES>>>(x, b, out);
}